// round 12
// baseline (speedup 1.0000x reference)
#include <cuda_runtime.h>
#include <cuda_bf16.h>
#include <cstdint>

// ---------------------------------------------------------------------------
// RowLSTM: x(16,64,64,64), Wi(512,64,1,3), bi(512), Wh(512,128), bh(512)
// out: (16,128,64,64) fp32
// Phase 1 (i2h): mma.sync bf16 3-pass hi/lo conv-GEMM (R8 winner, unchanged)
// Phase 2 (rec): mma.sync 2-pass; warp owns mt {w,w+8,w+16,w+24} so each
//   thread's D frags hold ALL 4 gate types for its (d,col) pairs ->
//   in-register pointwise, zero gate-shuffle smem, ONE barrier per row.
// ---------------------------------------------------------------------------

#define B_  16
#define C_  64
#define H_  64
#define W_  64
#define HID_ 128
#define G_  512
#define K_  192

static __device__ float    g_i2h[(size_t)H_ * B_ * W_ * G_];   // [h][b][w][g]
static __device__ uint32_t g_xTh[(size_t)B_ * H_ * 66 * 32];   // [b][h][wp][cq] bf16x2 hi
static __device__ uint32_t g_xTl[(size_t)B_ * H_ * 66 * 32];   // lo
static __device__ uint32_t g_WiFh[49152];                      // [kw][kt][mt][lane][reg]
static __device__ uint32_t g_WiFl[49152];
static __device__ uint32_t g_WhFh[32768];                      // [kt(8)][mt(32)][lane(32)][reg(4)]

__device__ __forceinline__ float sigmf(float v) {
    return __fdividef(1.0f, 1.0f + __expf(-v));
}
__device__ __forceinline__ float tanhf_(float v) {
    return __fdividef(2.0f, 1.0f + __expf(-2.0f * v)) - 1.0f;
}
__device__ __forceinline__ uint32_t pkbf(float a, float b) {
    __nv_bfloat162 t = __floats2bfloat162_rn(a, b);
    return *reinterpret_cast<uint32_t*>(&t);
}
__device__ __forceinline__ void split2(float v, float& hi, float& lo) {
    __nv_bfloat16 h = __float2bfloat16_rn(v);
    hi = __bfloat162float(h);
    lo = v - hi;
}
__device__ __forceinline__ void mma_bf16(float d[4], const uint32_t a[4], const uint32_t b[2]) {
    asm volatile(
        "mma.sync.aligned.m16n8k16.row.col.f32.bf16.bf16.f32 "
        "{%0,%1,%2,%3},{%4,%5,%6,%7},{%8,%9},{%0,%1,%2,%3};"
        : "+f"(d[0]), "+f"(d[1]), "+f"(d[2]), "+f"(d[3])
        : "r"(a[0]), "r"(a[1]), "r"(a[2]), "r"(a[3]), "r"(b[0]), "r"(b[1]));
}

// ---------------------------------------------------------------------------
// Prep 1: x -> xT hi/lo bf16x2, layout [b][h][wp(66)][cq(32)], zero-padded ends
// ---------------------------------------------------------------------------
__global__ void __launch_bounds__(256)
prep_x(const float* __restrict__ x)
{
    const int b = blockIdx.x >> 6, h = blockIdx.x & 63;
    const int tid = threadIdx.x;
    __shared__ float xt[64][65];
    for (int idx = tid; idx < 4096; idx += 256) {
        int c = idx >> 6, w = idx & 63;
        xt[c][w] = x[(((size_t)b * C_ + c) * H_ + h) * W_ + w];
    }
    __syncthreads();
    for (int idx = tid; idx < 66 * 32; idx += 256) {
        int wp = idx >> 5, cq = idx & 31, c0 = cq * 2;
        uint32_t vh = 0u, vl = 0u;
        if (wp >= 1 && wp <= 64) {
            int w = wp - 1;
            float ah, al, bh, bl;
            split2(xt[c0][w], ah, al);
            split2(xt[c0 + 1][w], bh, bl);
            vh = pkbf(ah, bh);
            vl = pkbf(al, bl);
        }
        size_t o = (((size_t)b * H_ + h) * 66 + wp) * 32 + cq;
        g_xTh[o] = vh;
        g_xTl[o] = vl;
    }
}

// ---------------------------------------------------------------------------
// Prep 2: Wi -> fragment-linear hi/lo [kw(3)][kt(4)][mt(32)][lane(32)][reg(4)]
// ---------------------------------------------------------------------------
__global__ void __launch_bounds__(512)
prep_wif(const float* __restrict__ Wi)
{
    int gid = blockIdx.x * 512 + threadIdx.x;   // < 49152
    int reg = gid & 3, lane = (gid >> 2) & 31, mt = (gid >> 7) & 31;
    int kt = (gid >> 12) & 3, kw = gid >> 14;
    int grp = lane >> 2, tig = lane & 3;
    int g  = mt * 16 + grp + 8 * (reg & 1);
    int c0 = kt * 16 + 2 * tig + 8 * (reg >> 1);
    float a = Wi[(size_t)g * K_ + c0 * 3 + kw];
    float b = Wi[(size_t)g * K_ + (c0 + 1) * 3 + kw];
    float ah, al, bh, bl;
    split2(a, ah, al);
    split2(b, bh, bl);
    g_WiFh[gid] = pkbf(ah, bh);
    g_WiFl[gid] = pkbf(al, bl);
}

// ---------------------------------------------------------------------------
// Prep 3: Wh -> fragment-linear hi only [kt(8)][mt(32)][lane(32)][reg(4)]
// ---------------------------------------------------------------------------
__global__ void __launch_bounds__(512)
prep_whf(const float* __restrict__ Wh)
{
    int gid = blockIdx.x * 512 + threadIdx.x;   // < 32768
    int reg = gid & 3, lane = (gid >> 2) & 31, mt = (gid >> 7) & 31;
    int kt = gid >> 12;
    int grp = lane >> 2, tig = lane & 3;
    int g = mt * 16 + grp + 8 * (reg & 1);
    int k = kt * 16 + 2 * tig + 8 * (reg >> 1);
    float a = Wh[(size_t)g * HID_ + k];
    float b = Wh[(size_t)g * HID_ + k + 1];
    g_WhFh[gid] = pkbf(__bfloat162float(__float2bfloat16_rn(a)),
                       __bfloat162float(__float2bfloat16_rn(b)));
}

// ---------------------------------------------------------------------------
// Kernel A: i2h (R8 winner, unchanged). Grid 512 = gc(8) x b(16) x ic(4).
// ---------------------------------------------------------------------------
#define A_HI  0
#define A_LO  24576
#define XS_HI 49152
#define XS_LO 68160
#define STGB  49152
#define SMEM_I2H 87168

__global__ void __launch_bounds__(256, 2)
i2h_kernel()
{
    extern __shared__ char sm[];
    const int gc = blockIdx.x & 7;
    const int b  = (blockIdx.x >> 3) & 15;
    const int ic = blockIdx.x >> 7;
    const int tid  = threadIdx.x;
    const int lane = tid & 31;
    const int warp = tid >> 5;
    const int wg   = warp >> 2;
    const int wn   = warp & 3;
    const int grp  = lane >> 2;
    const int tig  = lane & 3;

    uint4* ah4 = reinterpret_cast<uint4*>(sm + A_HI);
    uint4* al4 = reinterpret_cast<uint4*>(sm + A_LO);
    const uint4* wfh4 = reinterpret_cast<const uint4*>(g_WiFh);
    const uint4* wfl4 = reinterpret_cast<const uint4*>(g_WiFl);

    for (int idx = tid; idx < 1536; idx += 256) {
        int ln = idx & 31, gt = (idx >> 5) & 3, kt = (idx >> 7) & 3, kw = idx >> 9;
        int src = ((kw * 4 + kt) * 32 + gc * 4 + gt) * 32 + ln;
        int dst = ((kw * 4 + kt) * 4 + gt) * 32 + ln;
        ah4[dst] = wfh4[src];
        al4[dst] = wfl4[src];
    }

    int nbase[4];
#pragma unroll
    for (int nt2 = 0; nt2 < 4; nt2++) {
        int n = (wn * 4 + nt2) * 8 + grp;
        int hs = n >> 6, w = n & 63;
        nbase[nt2] = hs * 9504 + w * 144;
    }

    uint32_t* xh = reinterpret_cast<uint32_t*>(sm + XS_HI);
    uint32_t* xl = reinterpret_cast<uint32_t*>(sm + XS_LO);
    float* stg = reinterpret_cast<float*>(sm + STGB);

    for (int i = 0; i < 8; i++) {
        const int it = ic * 8 + i;
        const int h0 = it * 2;
        __syncthreads();

        for (int idx = tid; idx < 2 * 66 * 32; idx += 256) {
            int hs = idx >> 11;
            int rem = idx - hs * 2112;
            int wp = rem >> 5, cq = rem & 31;
            size_t g = (((size_t)b * H_ + h0 + hs) * 66 + wp) * 32 + cq;
            int d = hs * 2376 + wp * 36 + cq;
            xh[d] = g_xTh[g];
            xl[d] = g_xTl[g];
        }
        __syncthreads();

        float d[2][4][4];
#pragma unroll
        for (int a = 0; a < 2; a++)
#pragma unroll
            for (int c = 0; c < 4; c++)
#pragma unroll
                for (int r = 0; r < 4; r++) d[a][c][r] = 0.f;

#pragma unroll
        for (int kk = 0; kk < 12; kk++) {
            const int kw = kk >> 2, kt = kk & 3;
            const int koff = kw * 144 + kt * 32 + tig * 4;

            uint4 ahf[2], alf[2];
#pragma unroll
            for (int gt2 = 0; gt2 < 2; gt2++) {
                int fo = (kk * 4 + wg * 2 + gt2) * 32 + lane;
                ahf[gt2] = ah4[fo];
                alf[gt2] = al4[fo];
            }
            uint32_t bhf[4][2], blf[4][2];
#pragma unroll
            for (int nt2 = 0; nt2 < 4; nt2++) {
                int off = nbase[nt2] + koff;
                bhf[nt2][0] = *reinterpret_cast<const uint32_t*>(sm + XS_HI + off);
                bhf[nt2][1] = *reinterpret_cast<const uint32_t*>(sm + XS_HI + off + 16);
                blf[nt2][0] = *reinterpret_cast<const uint32_t*>(sm + XS_LO + off);
                blf[nt2][1] = *reinterpret_cast<const uint32_t*>(sm + XS_LO + off + 16);
            }
#pragma unroll
            for (int gt2 = 0; gt2 < 2; gt2++)
#pragma unroll
                for (int nt2 = 0; nt2 < 4; nt2++)
                    mma_bf16(d[gt2][nt2], &ahf[gt2].x, bhf[nt2]);
#pragma unroll
            for (int gt2 = 0; gt2 < 2; gt2++)
#pragma unroll
                for (int nt2 = 0; nt2 < 4; nt2++)
                    mma_bf16(d[gt2][nt2], &ahf[gt2].x, blf[nt2]);
#pragma unroll
            for (int gt2 = 0; gt2 < 2; gt2++)
#pragma unroll
                for (int nt2 = 0; nt2 < 4; nt2++)
                    mma_bf16(d[gt2][nt2], &alf[gt2].x, bhf[nt2]);
        }
        __syncthreads();

#pragma unroll
        for (int gt2 = 0; gt2 < 2; gt2++) {
            int g0 = (wg * 2 + gt2) * 16 + grp;
#pragma unroll
            for (int nt2 = 0; nt2 < 4; nt2++) {
                int n0 = (wn * 4 + nt2) * 8 + 2 * tig;
                stg[n0 * 64 + g0]           = d[gt2][nt2][0];
                stg[(n0 + 1) * 64 + g0]     = d[gt2][nt2][1];
                stg[n0 * 64 + g0 + 8]       = d[gt2][nt2][2];
                stg[(n0 + 1) * 64 + g0 + 8] = d[gt2][nt2][3];
            }
        }
        __syncthreads();

#pragma unroll
        for (int u = 0; u < 8; u++) {
            int idx = tid + u * 256;
            int n = idx >> 4;
            int q4 = idx & 15;
            float4 v = *reinterpret_cast<const float4*>(&stg[n * 64 + q4 * 4]);
            size_t dst = ((size_t)(h0 + (n >> 6)) * B_ + b) * (W_ * G_)
                       + (size_t)(n & 63) * G_ + gc * 64 + q4 * 4;
            *reinterpret_cast<float4*>(&g_i2h[dst]) = v;
        }
    }
}

// ---------------------------------------------------------------------------
// Kernel B: rec v2. 128 blocks = (b, w8), 256 threads = 8 warps.
// Warp w owns mt {w, w+8, w+16, w+24} -> thread has i/f/o/g for its (d,col)
// pairs in D regs. Wh-hi frags staged once in smem. h/hfp double-buffered
// by row parity; ONE __syncthreads per row.
// ---------------------------------------------------------------------------
#define HBS 136          // h bf16 row stride (bf16 units) = 272 B
#define HP  10           // hfp row stride (floats)
#define WHS_OFF 0        // Wh frags: 8192 uint4 = 131072 B
#define HBH_OFF 131072   // 2 bufs x 8 cols x HBS bf16 = 4352 B
#define HBL_OFF (131072 + 4352)
#define HFP_OFF (131072 + 8704)          // 2 bufs x 128*HP floats = 10240 B
#define SMEM_REC (131072 + 8704 + 10240) // 150016

__global__ void __launch_bounds__(256, 1)
rec_kernel(const float* __restrict__ bi, const float* __restrict__ bh,
           float* __restrict__ out)
{
    extern __shared__ char sm[];
    uint4* whs = reinterpret_cast<uint4*>(sm + WHS_OFF);
    __nv_bfloat16* hbh = reinterpret_cast<__nv_bfloat16*>(sm + HBH_OFF);
    __nv_bfloat16* hbl = reinterpret_cast<__nv_bfloat16*>(sm + HBL_OFF);
    float* hfp = reinterpret_cast<float*>(sm + HFP_OFF);

    const int b  = blockIdx.x >> 3;
    const int w0 = (blockIdx.x & 7) * 8;
    const int t  = threadIdx.x;
    const int lane = t & 31;
    const int warp = t >> 5;        // 0..7
    const int grp  = lane >> 2;     // 0..7
    const int tig  = lane & 3;      // 0..3

    // stage Wh-hi fragments (coalesced, once)
    const uint4* wgl = reinterpret_cast<const uint4*>(g_WhFh);
    for (int i = t; i < 8192; i += 256) whs[i] = wgl[i];

    // zero h buffer 0
    const __nv_bfloat16 bz = __float2bfloat16(0.f);
    for (int p = t; p < 8 * HBS; p += 256) { hbh[p] = bz; hbl[p] = bz; }
    __syncthreads();

    const int d0 = 16 * warp + grp;     // gate-d base (pairs use d0, d0+8)
    const int c0 = 2 * tig;             // col base (pairs use c0, c0+1)

    // bias[m][j]: gate type m, d = d0 + 8j
    float bias[4][2];
#pragma unroll
    for (int m = 0; m < 4; m++)
#pragma unroll
        for (int j = 0; j < 2; j++) {
            int g = m * HID_ + d0 + 8 * j;
            bias[m][j] = bi[g] + bh[g];
        }
    float creg[4] = {0.f, 0.f, 0.f, 0.f};   // pair r: d=d0+8*(r>>1), col=c0+(r&1)

    const int bofs = grp * (HBS * 2) + tig * 4;   // byte offset in h buffers

    for (int row = 0; row < H_; row++) {
        const int rb = row & 1;
        const int nb = rb ^ 1;

        // ---- prefetch i2h gates: 16 scalar loads ----
        const float* ivb = g_i2h + (((size_t)row * B_ + b) * W_ + w0) * G_;
        float ivr[4][4];   // [m][pair]
#pragma unroll
        for (int m = 0; m < 4; m++) {
            const float* p0 = ivb + (size_t)c0 * G_ + m * HID_ + d0;
            ivr[m][0] = __ldg(p0);
            ivr[m][1] = __ldg(p0 + G_);
            ivr[m][2] = __ldg(p0 + 8);
            ivr[m][3] = __ldg(p0 + G_ + 8);
        }

        // ---- mma: 4 mt x 8 kt x 2 passes; split accumulators (hi/lo pass) ----
        float Dh[4][4], Dl[4][4];
#pragma unroll
        for (int m = 0; m < 4; m++)
#pragma unroll
            for (int r = 0; r < 4; r++) { Dh[m][r] = 0.f; Dl[m][r] = 0.f; }

        const __nv_bfloat16* hbh_r = hbh + rb * 8 * HBS;
        const __nv_bfloat16* hbl_r = hbl + rb * 8 * HBS;
#pragma unroll
        for (int kt = 0; kt < 8; kt++) {
            uint32_t bhf[2], blf[2];
            const char* ph = reinterpret_cast<const char*>(hbh_r) + bofs + kt * 32;
            const char* pl = reinterpret_cast<const char*>(hbl_r) + bofs + kt * 32;
            bhf[0] = *reinterpret_cast<const uint32_t*>(ph);
            bhf[1] = *reinterpret_cast<const uint32_t*>(ph + 16);
            blf[0] = *reinterpret_cast<const uint32_t*>(pl);
            blf[1] = *reinterpret_cast<const uint32_t*>(pl + 16);
#pragma unroll
            for (int m = 0; m < 4; m++) {
                uint4 a = whs[((kt * 32) + (warp + m * 8)) * 32 + lane];
                mma_bf16(Dh[m], &a.x, bhf);
                mma_bf16(Dl[m], &a.x, blf);
            }
        }

        // ---- in-register pointwise: 4 (d,col) pairs per thread ----
        __nv_bfloat16* hbh_w = hbh + nb * 8 * HBS;
        __nv_bfloat16* hbl_w = hbl + nb * 8 * HBS;
        float* hfp_w = hfp + rb * HID_ * HP;
#pragma unroll
        for (int r = 0; r < 4; r++) {
            const int j   = r >> 1;
            const int col = c0 + (r & 1);
            const int d   = d0 + 8 * j;
            float ig = Dh[0][r] + Dl[0][r] + ivr[0][r] + bias[0][j];
            float fg = Dh[1][r] + Dl[1][r] + ivr[1][r] + bias[1][j];
            float og = Dh[2][r] + Dl[2][r] + ivr[2][r] + bias[2][j];
            float gg = Dh[3][r] + Dl[3][r] + ivr[3][r] + bias[3][j];
            float cv = sigmf(fg) * creg[r] + sigmf(ig) * tanhf_(gg);
            float hv = sigmf(og) * tanhf_(cv);
            creg[r] = cv;
            hfp_w[d * HP + col] = hv;
            float hh, hl;
            split2(hv, hh, hl);
            hbh_w[col * HBS + d] = __float2bfloat16(hh);
            hbl_w[col * HBS + d] = __float2bfloat16(hl);
        }
        __syncthreads();   // the ONE barrier: h(row+1) + hfp(row) visible

        // ---- out write (reads hfp buf rb; next pointwise writes buf nb) ----
        if (t < HID_) {
            const int d = t;
            const float* hp = hfp + rb * HID_ * HP + d * HP;
            float4 v0 = make_float4(hp[0], hp[1], hp[2], hp[3]);
            float4 v1 = make_float4(hp[4], hp[5], hp[6], hp[7]);
            float* op = out + ((((size_t)b * HID_ + d) * H_) + row) * W_ + w0;
            *reinterpret_cast<float4*>(op)     = v0;
            *reinterpret_cast<float4*>(op + 4) = v1;
        }
    }
}

// ---------------------------------------------------------------------------
extern "C" void kernel_launch(void* const* d_in, const int* in_sizes, int n_in,
                              void* d_out, int out_size)
{
    (void)in_sizes; (void)n_in; (void)out_size;
    const float* x  = (const float*)d_in[0];
    const float* Wi = (const float*)d_in[1];
    const float* bi = (const float*)d_in[2];
    const float* Wh = (const float*)d_in[3];
    const float* bh = (const float*)d_in[4];
    float* out = (float*)d_out;

    static bool attr_set = false;
    if (!attr_set) {
        cudaFuncSetAttribute(i2h_kernel, cudaFuncAttributeMaxDynamicSharedMemorySize, SMEM_I2H);
        cudaFuncSetAttribute(rec_kernel, cudaFuncAttributeMaxDynamicSharedMemorySize, SMEM_REC);
        attr_set = true;
    }

    prep_x<<<B_ * H_, 256>>>(x);
    prep_wif<<<96, 512>>>(Wi);
    prep_whf<<<64, 512>>>(Wh);
    i2h_kernel<<<512, 256, SMEM_I2H>>>();
    rec_kernel<<<B_ * (W_ / 8), 256, SMEM_REC>>>(bi, bh, out);
}